// round 10
// baseline (speedup 1.0000x reference)
#include <cuda_runtime.h>
#include <cuda_bf16.h>

// Problem constants: B=4, S=2048, E=1024, H=16, D=64, M=B*S=8192
// Scratch (device globals; allocation-free per harness rules)
static __device__ float g_q[8388608];    // [B,H,S,D], pre-scaled by 1/sqrt(D)
static __device__ float g_k[8388608];    // [B,H,S,D]
static __device__ float g_v[8388608];    // [B,H,S,D]
static __device__ float g_attn[8388608]; // [B,S,E]

// ---- packed f32x2 helpers (sm_103a FFMA2: only reachable via PTX) ----------
__device__ __forceinline__ unsigned long long f32x2_pack(float lo, float hi) {
    unsigned long long r;
    asm("mov.b64 %0, {%1, %2};" : "=l"(r) : "f"(lo), "f"(hi));
    return r;
}
__device__ __forceinline__ void f32x2_unpack(float& lo, float& hi, unsigned long long v) {
    asm("mov.b64 {%0, %1}, %2;" : "=f"(lo), "=f"(hi) : "l"(v));
}
__device__ __forceinline__ void f32x2_fma(unsigned long long& d,
                                          unsigned long long a,
                                          unsigned long long b) {
    asm("fma.rn.f32x2 %0, %1, %2, %3;" : "=l"(d) : "l"(a), "l"(b), "l"(d));
}
__device__ __forceinline__ void f32x2_mul(unsigned long long& d,
                                          unsigned long long a,
                                          unsigned long long b) {
    asm("mul.rn.f32x2 %0, %1, %2;" : "=l"(d) : "l"(a), "l"(b));
}

// ---------------------------------------------------------------------------
// 128x128x16 SGEMM, register-prefetch + double-buffered smem (1 sync/iter),
// inner product in packed f32x2. B pairs loaded PRE-PACKED from smem as
// ulonglong2; A broadcast packs overlap the FMA pipe (20 slots of slack).
//   C[m,f] = sum_k A[m,k] * W[f,k] + bias[f]
// MODE 1: A = query, scatter into g_q/g_k/g_v (q scaled by 0.125), Nd=3072
// MODE 2: A = g_attn, plain write to Cout, Nd=1024
// ---------------------------------------------------------------------------
template <int MODE>
__global__ void __launch_bounds__(256)
sgemm_kernel(const float* __restrict__ Ain, const float* __restrict__ W,
             const float* __restrict__ bias, float* __restrict__ Cout)
{
    constexpr int Kd = 1024;
    constexpr int Nd = (MODE == 1) ? 3072 : 1024;
    __shared__ float As[2][16][132];   // [buf][k][m], +4 pad -> 2-way store conflicts
    __shared__ float Bs[2][16][132];   // [buf][k][n]  (132*4=528B row: 16B-divisible)

    const float* A = (MODE == 2) ? g_attn : Ain;
    const int tid = threadIdx.x;
    const int tm = tid >> 4, tn = tid & 15;
    const int m0 = blockIdx.y * 128, n0 = blockIdx.x * 128;
    const int lr = tid >> 2;          // 0..63 (row within half-tile)
    const int lk = (tid & 3) << 2;    // 0,4,8,12 (k float4 base)

    const float* Ap = A + (size_t)(m0 + lr) * Kd + lk;
    const float* Wp = W + (size_t)(n0 + lr) * Kd + lk;

    // acc2[i][j2]: packed pair of columns (2*j2, 2*j2+1) for row i.
    unsigned long long acc2[8][4];
#pragma unroll
    for (int i = 0; i < 8; i++)
#pragma unroll
        for (int j2 = 0; j2 < 4; j2++) acc2[i][j2] = f32x2_pack(0.f, 0.f);

    // Load k-tile 0 into registers, store to buffer 0
    float4 pa0 = *(const float4*)(Ap);
    float4 pa1 = *(const float4*)(Ap + (size_t)64 * Kd);
    float4 pb0 = *(const float4*)(Wp);
    float4 pb1 = *(const float4*)(Wp + (size_t)64 * Kd);

    As[0][lk+0][lr]    = pa0.x; As[0][lk+1][lr]    = pa0.y; As[0][lk+2][lr]    = pa0.z; As[0][lk+3][lr]    = pa0.w;
    As[0][lk+0][lr+64] = pa1.x; As[0][lk+1][lr+64] = pa1.y; As[0][lk+2][lr+64] = pa1.z; As[0][lk+3][lr+64] = pa1.w;
    Bs[0][lk+0][lr]    = pb0.x; Bs[0][lk+1][lr]    = pb0.y; Bs[0][lk+2][lr]    = pb0.z; Bs[0][lk+3][lr]    = pb0.w;
    Bs[0][lk+0][lr+64] = pb1.x; Bs[0][lk+1][lr+64] = pb1.y; Bs[0][lk+2][lr+64] = pb1.z; Bs[0][lk+3][lr+64] = pb1.w;
    __syncthreads();

    int rd = 0;
    for (int kt = 0; kt < Kd; kt += 16) {
        const bool more = (kt + 16 < Kd);
        // Prefetch the NEXT k-tile while computing this one (hides LDG latency)
        if (more) {
            pa0 = *(const float4*)(Ap + kt + 16);
            pa1 = *(const float4*)(Ap + kt + 16 + (size_t)64 * Kd);
            pb0 = *(const float4*)(Wp + kt + 16);
            pb1 = *(const float4*)(Wp + kt + 16 + (size_t)64 * Kd);
        }

#pragma unroll
        for (int k = 0; k < 16; k++) {
            float4 av0 = *(const float4*)&As[rd][k][tm*4];
            float4 av1 = *(const float4*)&As[rd][k][tm*4 + 64];
            // B column pairs arrive pre-packed (contiguous in smem)
            const ulonglong2 b01 = *(const ulonglong2*)&Bs[rd][k][tn*4];
            const ulonglong2 b23 = *(const ulonglong2*)&Bs[rd][k][tn*4 + 64];
            float am[8] = {av0.x, av0.y, av0.z, av0.w, av1.x, av1.y, av1.z, av1.w};
#pragma unroll
            for (int i = 0; i < 8; i++) {
                const unsigned long long pa = f32x2_pack(am[i], am[i]);  // ALU pipe
                f32x2_fma(acc2[i][0], pa, b01.x);
                f32x2_fma(acc2[i][1], pa, b01.y);
                f32x2_fma(acc2[i][2], pa, b23.x);
                f32x2_fma(acc2[i][3], pa, b23.y);
            }
        }

        if (more) {
            const int wr = rd ^ 1;  // last read at kt-16; readers drained by that iter's sync
            As[wr][lk+0][lr]    = pa0.x; As[wr][lk+1][lr]    = pa0.y; As[wr][lk+2][lr]    = pa0.z; As[wr][lk+3][lr]    = pa0.w;
            As[wr][lk+0][lr+64] = pa1.x; As[wr][lk+1][lr+64] = pa1.y; As[wr][lk+2][lr+64] = pa1.z; As[wr][lk+3][lr+64] = pa1.w;
            Bs[wr][lk+0][lr]    = pb0.x; Bs[wr][lk+1][lr]    = pb0.y; Bs[wr][lk+2][lr]    = pb0.z; Bs[wr][lk+3][lr]    = pb0.w;
            Bs[wr][lk+0][lr+64] = pb1.x; Bs[wr][lk+1][lr+64] = pb1.y; Bs[wr][lk+2][lr+64] = pb1.z; Bs[wr][lk+3][lr+64] = pb1.w;
            __syncthreads();
            rd = wr;
        }
    }

    // Epilogue (bias fetched as aligned float4; unpack f32x2 accumulators)
#pragma unroll
    for (int ih = 0; ih < 2; ih++)
#pragma unroll
    for (int i = 0; i < 4; i++) {
        const int row = m0 + ih*64 + tm*4 + i;
#pragma unroll
        for (int jh = 0; jh < 2; jh++) {
            const int colb = n0 + jh*64 + tn*4;
            const float4 b4 = *(const float4*)(bias + colb);
            float a0, a1, a2, a3;
            f32x2_unpack(a0, a1, acc2[ih*4+i][jh*2+0]);
            f32x2_unpack(a2, a3, acc2[ih*4+i][jh*2+1]);
            float4 v;
            v.x = a0 + b4.x;
            v.y = a1 + b4.y;
            v.z = a2 + b4.z;
            v.w = a3 + b4.w;
            if (MODE == 1) {
                const int which = colb >> 10;       // 0=q, 1=k, 2=v
                const int e  = colb & 1023;
                const int h  = e >> 6, db = e & 63;
                const int b  = row >> 11, s = row & 2047;
                const size_t idx = ((size_t)((b*16 + h)*2048 + s))*64 + db;
                if (which == 0) {
                    v.x *= 0.125f; v.y *= 0.125f; v.z *= 0.125f; v.w *= 0.125f; // fold 1/sqrt(64)
                    *(float4*)&g_q[idx] = v;
                } else if (which == 1) {
                    *(float4*)&g_k[idx] = v;
                } else {
                    *(float4*)&g_v[idx] = v;
                }
            } else {
                *(float4*)&Cout[(size_t)row * Nd + colb] = v;
            }
        }
    }
}

// ---------------------------------------------------------------------------
// Flash attention, causal. One block = one (b,h) x one 64-row q tile.
// 256 threads as 16x16 grid, 4x4 micro-tiles. D=64.
// Dynamic smem 112KB: Qd[32K dup] + K[16K] + V[2][16K] + Pd[32K dup].
// Two __syncthreads() per k-tile (commit-sync, p-sync).
// ALL f32x2 operands now load PRE-PACKED from smem (ulonglong2): K/V pairs
// are contiguous; Q and P broadcasts are stored duplicated. Zero pack movs
// in the score loop, zero in the PV loop.
// ---------------------------------------------------------------------------
#define ATTN_SMEM_BYTES (112 * 1024)

__global__ void __launch_bounds__(256, 2)
attn_kernel()
{
    extern __shared__ float smem[];
    float* Qd = smem;                  // [d][2r swizzled-by-pair]  8192 floats
    float* Ks = smem + 8192;           // [d][c^swz(d)]             4096 floats
    float* Vs = smem + 12288;          // [2][c][d']                8192 floats
    float* Pd = smem + 20480;          // [r][2c duplicated]        8192 floats

    const int tid = threadIdx.x;
    const int tm = tid >> 4, tn = tid & 15;
    const int qt = gridDim.x - 1 - blockIdx.x;  // heavy tiles launch first
    const int bh = blockIdx.y;
    const int q0 = qt * 64;
    const float* Qg = g_q + ((size_t)bh*2048 + q0) * 64;
    const float* Kg = g_k + (size_t)bh * 2048 * 64;
    const float* Vg = g_v + (size_t)bh * 2048 * 64;

    // Per-thread load coordinates (fixed across tiles)
    const int plr  = tid >> 4;           // row base for this thread
    const int pd4  = (tid & 15) << 2;    // d-offset (float4)
    const int pswz = ((pd4 >> 2) & 7) << 2;

    // Load Q tile, store DUPLICATED + pair-swizzled: Qd[d][2*(r^swz)+{0,1}]=q
#pragma unroll
    for (int it = 0; it < 4; it++) {
        const int rr = plr + it*16;
        float4 v = *(const float4*)(Qg + (size_t)rr*64 + pd4);
        const int col2 = (rr ^ pswz) << 1;
        *(float2*)&Qd[(pd4+0)*128 + col2] = make_float2(v.x, v.x);
        *(float2*)&Qd[(pd4+1)*128 + col2] = make_float2(v.y, v.y);
        *(float2*)&Qd[(pd4+2)*128 + col2] = make_float2(v.z, v.z);
        *(float2*)&Qd[(pd4+3)*128 + col2] = make_float2(v.w, v.w);
    }

    float mrow[4], lrow[4];
    unsigned long long O2[4][2];  // packed pairs of O columns (tn*4+{0,1},{2,3})
#pragma unroll
    for (int i = 0; i < 4; i++) {
        mrow[i] = -1e30f; lrow[i] = 0.f;
        O2[i][0] = f32x2_pack(0.f, 0.f);
        O2[i][1] = f32x2_pack(0.f, 0.f);
    }

    // Prefetch K/V tile 0 into registers
    float4 pk[4], pv[4];
#pragma unroll
    for (int it = 0; it < 4; it++) {
        pk[it] = *(const float4*)(Kg + (size_t)(plr + it*16)*64 + pd4);
        const int idx = tid + it*256;
        pv[it] = *(const float4*)(Vg + (size_t)(idx >> 4)*64 + ((idx & 15) << 2));
    }

    for (int jt = 0; jt <= qt; jt++) {
        float* Vcur = Vs + (jt & 1) * 4096;
        // Commit prefetched K (transposed+swizzled) and V (to buffer jt&1).
#pragma unroll
        for (int it = 0; it < 4; it++) {
            const int rr = plr + it*16;
            const int col = rr ^ pswz;
            Ks[(pd4+0)*64 + col] = pk[it].x;
            Ks[(pd4+1)*64 + col] = pk[it].y;
            Ks[(pd4+2)*64 + col] = pk[it].z;
            Ks[(pd4+3)*64 + col] = pk[it].w;
            const int idx = tid + it*256;
            *(float4*)&Vcur[(idx >> 4)*64 + ((idx & 15) << 2)] = pv[it];
        }
        __syncthreads();  // commit-sync: K/V/Qd visible; PV(jt-1) fully drained

        // Issue loads for the NEXT tile; they complete during score+softmax+PV
        if (jt < qt) {
            const int k1 = (jt + 1) * 64;
#pragma unroll
            for (int it = 0; it < 4; it++) {
                pk[it] = *(const float4*)(Kg + (size_t)(k1 + plr + it*16)*64 + pd4);
                const int idx = tid + it*256;
                pv[it] = *(const float4*)(Vg + (size_t)(k1 + (idx >> 4))*64 + ((idx & 15) << 2));
            }
        }

        // Scores: S[r][c] = sum_d Q[r][d]*K[c][d]  (Q pre-scaled), FFMA2.
        // All operands pre-packed: q dups from Qd, k pairs from Ks.
        unsigned long long sacc2[4][2];
#pragma unroll
        for (int i = 0; i < 4; i++) {
            sacc2[i][0] = f32x2_pack(0.f, 0.f);
            sacc2[i][1] = f32x2_pack(0.f, 0.f);
        }

#pragma unroll
        for (int d4 = 0; d4 < 16; d4++) {
            const int swz = (d4 & 7) << 2;
            const int qb = ((tm*4) ^ swz) << 1;
            const int kcol = (tn*4) ^ swz;
#pragma unroll
            for (int dd = 0; dd < 4; dd++) {
                const int d = d4*4 + dd;
                const ulonglong2 q01 = *(const ulonglong2*)&Qd[d*128 + qb];
                const ulonglong2 q23 = *(const ulonglong2*)&Qd[d*128 + qb + 4];
                const ulonglong2 kk  = *(const ulonglong2*)&Ks[d*64 + kcol];
                f32x2_fma(sacc2[0][0], q01.x, kk.x);
                f32x2_fma(sacc2[0][1], q01.x, kk.y);
                f32x2_fma(sacc2[1][0], q01.y, kk.x);
                f32x2_fma(sacc2[1][1], q01.y, kk.y);
                f32x2_fma(sacc2[2][0], q23.x, kk.x);
                f32x2_fma(sacc2[2][1], q23.x, kk.y);
                f32x2_fma(sacc2[3][0], q23.y, kk.x);
                f32x2_fma(sacc2[3][1], q23.y, kk.y);
            }
        }

        // Unpack scores for mask + softmax (scalar)
        float sacc[4][4];
#pragma unroll
        for (int i = 0; i < 4; i++) {
            f32x2_unpack(sacc[i][0], sacc[i][1], sacc2[i][0]);
            f32x2_unpack(sacc[i][2], sacc[i][3], sacc2[i][1]);
        }

        if (jt == qt) {  // causal mask on the diagonal tile
#pragma unroll
            for (int i = 0; i < 4; i++)
#pragma unroll
                for (int j2 = 0; j2 < 4; j2++)
                    if (tn*4 + j2 > tm*4 + i) sacc[i][j2] = -1e30f;
        }

        // Online softmax (row stats shared by the 16 lanes of each row group)
#pragma unroll
        for (int i = 0; i < 4; i++) {
            float mx = fmaxf(fmaxf(sacc[i][0], sacc[i][1]), fmaxf(sacc[i][2], sacc[i][3]));
#pragma unroll
            for (int off = 8; off >= 1; off >>= 1)
                mx = fmaxf(mx, __shfl_xor_sync(0xffffffffu, mx, off, 16));
            const float mnew  = fmaxf(mrow[i], mx);
            const float alpha = __expf(mrow[i] - mnew);
            float rs = 0.f;
#pragma unroll
            for (int j2 = 0; j2 < 4; j2++) {
                const float p = __expf(sacc[i][j2] - mnew);
                sacc[i][j2] = p;
                rs += p;
            }
#pragma unroll
            for (int off = 8; off >= 1; off >>= 1)
                rs += __shfl_xor_sync(0xffffffffu, rs, off, 16);
            lrow[i] = lrow[i]*alpha + rs;
            mrow[i] = mnew;
            const unsigned long long ap = f32x2_pack(alpha, alpha);
            f32x2_mul(O2[i][0], O2[i][0], ap);
            f32x2_mul(O2[i][1], O2[i][1], ap);
        }

        // Store P DUPLICATED: Pd[r][2c]=Pd[r][2c+1]=p (overwrite-safe per commit-sync)
#pragma unroll
        for (int i = 0; i < 4; i++) {
            const int rb = (tm*4 + i)*128 + tn*8;
            *(float4*)&Pd[rb]     = make_float4(sacc[i][0], sacc[i][0], sacc[i][1], sacc[i][1]);
            *(float4*)&Pd[rb + 4] = make_float4(sacc[i][2], sacc[i][2], sacc[i][3], sacc[i][3]);
        }
        __syncthreads();  // p-sync: Pd visible; score(jt) K-reads drained

        // O[r][d'] += sum_c P[r][c] * V[c][d']  (FFMA2; ALL operands pre-packed)
#pragma unroll 4
        for (int cb = 0; cb < 64; cb += 4) {
            // Duplicated P pairs for 4 columns x 4 rows: 2 ulonglong2 per row
            ulonglong2 pA[4], pB[4];
#pragma unroll
            for (int i = 0; i < 4; i++) {
                const int rb = (tm*4 + i)*128 + cb*2;
                pA[i] = *(const ulonglong2*)&Pd[rb];      // dup(c+0), dup(c+1)
                pB[i] = *(const ulonglong2*)&Pd[rb + 4];  // dup(c+2), dup(c+3)
            }
#pragma unroll
            for (int cc = 0; cc < 4; cc++) {
                const ulonglong2 vv = *(const ulonglong2*)&Vcur[(cb+cc)*64 + tn*4];
#pragma unroll
                for (int i = 0; i < 4; i++) {
                    const unsigned long long pp =
                        cc == 0 ? pA[i].x : cc == 1 ? pA[i].y : cc == 2 ? pB[i].x : pB[i].y;
                    f32x2_fma(O2[i][0], pp, vv.x);
                    f32x2_fma(O2[i][1], pp, vv.y);
                }
            }
        }
    }

    // Normalize and write [B,S,E]
    const int b = bh >> 4, h = bh & 15;
#pragma unroll
    for (int i = 0; i < 4; i++) {
        const float inv = 1.f / lrow[i];
        const int s = q0 + tm*4 + i;
        float o0, o1, o2, o3;
        f32x2_unpack(o0, o1, O2[i][0]);
        f32x2_unpack(o2, o3, O2[i][1]);
        float4 v = make_float4(o0*inv, o1*inv, o2*inv, o3*inv);
        *(float4*)&g_attn[((size_t)(b*2048 + s))*1024 + h*64 + tn*4] = v;
    }
}

// ---------------------------------------------------------------------------
extern "C" void kernel_launch(void* const* d_in, const int* in_sizes, int n_in,
                              void* d_out, int out_size)
{
    (void)in_sizes; (void)n_in; (void)out_size;
    const float* query = (const float*)d_in[0];  // [4,2048,1024]
    const float* w_in  = (const float*)d_in[1];  // [3072,1024]
    const float* b_in  = (const float*)d_in[2];  // [3072]
    const float* w_out = (const float*)d_in[3];  // [1024,1024]
    const float* b_out = (const float*)d_in[4];  // [1024]
    float* out = (float*)d_out;                  // [4,2048,1024] fp32

    // Opt-in to 112KB dynamic smem for the attention kernel. Unconditional
    // (idempotent host attribute set; no static guards per harness rules).
    cudaFuncSetAttribute(attn_kernel,
                         cudaFuncAttributeMaxDynamicSharedMemorySize,
                         ATTN_SMEM_BYTES);

    // 1) QKV projection + bias + q-scale + [B,H,S,D] scatter
    sgemm_kernel<1><<<dim3(24, 64), 256>>>(query, w_in, b_in, nullptr);
    // 2) causal flash attention -> g_attn [B,S,E]
    attn_kernel<<<dim3(32, 64), 256, ATTN_SMEM_BYTES>>>();
    // 3) output projection + bias -> d_out
    sgemm_kernel<2><<<dim3(8, 64), 256>>>(nullptr, w_out, b_out, out);
}

// round 13
// speedup vs baseline: 1.3015x; 1.3015x over previous
#include <cuda_runtime.h>
#include <cuda_bf16.h>
#include <cstdint>

// Problem constants: B=4, S=2048, E=1024, H=16, D=64, M=B*S=8192
static __device__ float g_q[8388608];    // [B,H,S,D], pre-scaled by 1/sqrt(D)
static __device__ float g_k[8388608];    // [B,H,S,D]
static __device__ float g_v[8388608];    // [B,H,S,D]
static __device__ float g_attn[8388608]; // [B,S,E]

// bf16x3 split operands (hi/lo), raw ushort
static __device__ __align__(256) unsigned short qa_hi[8388608], qa_lo[8388608]; // query
static __device__ __align__(256) unsigned short w1_hi[3145728], w1_lo[3145728]; // w_in
static __device__ __align__(256) unsigned short w2_hi[1048576], w2_lo[1048576]; // w_out
static __device__ __align__(256) unsigned short at_hi[8388608], at_lo[8388608]; // attn out

// ---- packed f32x2 helpers (attention kernel) -------------------------------
__device__ __forceinline__ unsigned long long f32x2_pack(float lo, float hi) {
    unsigned long long r;
    asm("mov.b64 %0, {%1, %2};" : "=l"(r) : "f"(lo), "f"(hi));
    return r;
}
__device__ __forceinline__ void f32x2_unpack(float& lo, float& hi, unsigned long long v) {
    asm("mov.b64 {%0, %1}, %2;" : "=f"(lo), "=f"(hi) : "l"(v));
}
__device__ __forceinline__ void f32x2_fma(unsigned long long& d,
                                          unsigned long long a,
                                          unsigned long long b) {
    asm("fma.rn.f32x2 %0, %1, %2, %3;" : "=l"(d) : "l"(a), "l"(b), "l"(d));
}
__device__ __forceinline__ void f32x2_mul(unsigned long long& d,
                                          unsigned long long a,
                                          unsigned long long b) {
    asm("mul.rn.f32x2 %0, %1, %2;" : "=l"(d) : "l"(a), "l"(b));
}

// ---- warp-mma helpers (baseline PTX, legal on compute_103) -----------------
__device__ __forceinline__ uint32_t smem_u32(const void* p) {
    uint32_t a;
    asm("{ .reg .u64 t; cvta.to.shared.u64 t, %1; cvt.u32.u64 %0, t; }" : "=r"(a) : "l"(p));
    return a;
}
__device__ __forceinline__ void cp16(uint32_t dst, const void* src) {
    asm volatile("cp.async.cg.shared.global [%0], [%1], 16;" :: "r"(dst), "l"(src) : "memory");
}
#define CP_COMMIT() asm volatile("cp.async.commit_group;" ::: "memory")
template <int N>
__device__ __forceinline__ void cp_wait() {
    asm volatile("cp.async.wait_group %0;" :: "n"(N) : "memory");
}
__device__ __forceinline__ void ldsm4(uint32_t* r, uint32_t addr) {
    asm volatile("ldmatrix.sync.aligned.m8n8.x4.shared.b16 {%0,%1,%2,%3}, [%4];"
        : "=r"(r[0]), "=r"(r[1]), "=r"(r[2]), "=r"(r[3]) : "r"(addr));
}
__device__ __forceinline__ void ldsm2(uint32_t* r, uint32_t addr) {
    asm volatile("ldmatrix.sync.aligned.m8n8.x2.shared.b16 {%0,%1}, [%2];"
        : "=r"(r[0]), "=r"(r[1]) : "r"(addr));
}
__device__ __forceinline__ void mma_bf16(float* c, const uint32_t* a, const uint32_t* b) {
    asm volatile(
        "mma.sync.aligned.m16n8k16.row.col.f32.bf16.bf16.f32 "
        "{%0,%1,%2,%3}, {%4,%5,%6,%7}, {%8,%9}, {%0,%1,%2,%3};"
        : "+f"(c[0]), "+f"(c[1]), "+f"(c[2]), "+f"(c[3])
        : "r"(a[0]), "r"(a[1]), "r"(a[2]), "r"(a[3]), "r"(b[0]), "r"(b[1]));
}

// ---------------------------------------------------------------------------
// fp32 -> bf16 hi/lo split. DST: 0=query, 1=w_in, 2=w_out, 3=g_attn.
// ---------------------------------------------------------------------------
template <int DST>
__global__ void __launch_bounds__(256)
convert_kernel(const float* __restrict__ src, int n4)
{
    unsigned short* hi = DST == 0 ? qa_hi : DST == 1 ? w1_hi : DST == 2 ? w2_hi : at_hi;
    unsigned short* lo = DST == 0 ? qa_lo : DST == 1 ? w1_lo : DST == 2 ? w2_lo : at_lo;
    const float* s = (DST == 3) ? g_attn : src;
    const int i = blockIdx.x * blockDim.x + threadIdx.x;
    if (i >= n4) return;
    float4 v = ((const float4*)s)[i];
    __nv_bfloat16 hx = __float2bfloat16_rn(v.x);
    __nv_bfloat16 hy = __float2bfloat16_rn(v.y);
    __nv_bfloat16 hz = __float2bfloat16_rn(v.z);
    __nv_bfloat16 hw = __float2bfloat16_rn(v.w);
    ushort4 h;
    h.x = __bfloat16_as_ushort(hx); h.y = __bfloat16_as_ushort(hy);
    h.z = __bfloat16_as_ushort(hz); h.w = __bfloat16_as_ushort(hw);
    ((ushort4*)hi)[i] = h;
    ushort4 l;
    l.x = __bfloat16_as_ushort(__float2bfloat16_rn(v.x - __bfloat162float(hx)));
    l.y = __bfloat16_as_ushort(__float2bfloat16_rn(v.y - __bfloat162float(hy)));
    l.z = __bfloat16_as_ushort(__float2bfloat16_rn(v.z - __bfloat162float(hz)));
    l.w = __bfloat16_as_ushort(__float2bfloat16_rn(v.w - __bfloat162float(hw)));
    ((ushort4*)lo)[i] = l;
}

// ---------------------------------------------------------------------------
// Warp-mma bf16x3 GEMM: C[m,f] = sum_k A[m,k]*W[f,k] + bias[f].
// 128x128 tile, 8 warps of 32(M)x64(N). mma.sync.m16n8k16 bf16->f32.
// D = Ahi*Bhi + Ahi*Blo + Alo*Bhi (lo*lo dropped; element err ~2^-16).
// cp.async double-buffered k64 chunks (4 tiles x 16KB x 2 bufs = 128KB smem).
// SW128 swizzle: ldmatrix row-sets hit 8 distinct 16B banks.
// MODE 1: A=qa, B=w1, scatter g_q/g_k/g_v (q scaled 0.125). MODE 2: A=at, B=w2.
// ---------------------------------------------------------------------------
#define MG_SMEM_BYTES 131072

template <int MODE>
__global__ void __launch_bounds__(256)
mma_gemm(const float* __restrict__ bias, float* __restrict__ Cout)
{
    constexpr int Kd = 1024;
    const unsigned short* Ahi = (MODE == 1) ? qa_hi : at_hi;
    const unsigned short* Alo = (MODE == 1) ? qa_lo : at_lo;
    const unsigned short* Bhi = (MODE == 1) ? w1_hi : w2_hi;
    const unsigned short* Blo = (MODE == 1) ? w1_lo : w2_lo;

    extern __shared__ char sm[];
    const uint32_t tb = smem_u32(sm);
    constexpr int AHI_O = 0, ALO_O = 16384, BHI_O = 32768, BLO_O = 49152;

    const int tid = threadIdx.x, lane = tid & 31, wid = tid >> 5;
    const int m0 = blockIdx.y * 128, n0 = blockIdx.x * 128;
    const int wm = (wid >> 1) * 32, wn = (wid & 1) * 64;

    // cp.async coords: thread -> (row 0..127, 64B-half)
    const int row = tid >> 1, half = tid & 1;
    const unsigned short* pAhi = Ahi + (size_t)(m0 + row) * Kd + half * 32;
    const unsigned short* pAlo = Alo + (size_t)(m0 + row) * Kd + half * 32;
    const unsigned short* pBhi = Bhi + (size_t)(n0 + row) * Kd + half * 32;
    const unsigned short* pBlo = Blo + (size_t)(n0 + row) * Kd + half * 32;
    uint32_t sw[4];
#pragma unroll
    for (int g = 0; g < 4; g++) {
        const uint32_t off = (uint32_t)(row * 128 + half * 64 + g * 16);
        sw[g] = off ^ ((off >> 3) & 0x70);
    }

    float acc[2][8][4];
#pragma unroll
    for (int mi = 0; mi < 2; mi++)
#pragma unroll
        for (int ni = 0; ni < 8; ni++)
#pragma unroll
            for (int e = 0; e < 4; e++) acc[mi][ni][e] = 0.f;

    // Prologue: chunk 0 -> buf 0
#pragma unroll
    for (int g = 0; g < 4; g++) {
        cp16(tb + AHI_O + sw[g], (const char*)pAhi + g * 16);
        cp16(tb + ALO_O + sw[g], (const char*)pAlo + g * 16);
        cp16(tb + BHI_O + sw[g], (const char*)pBhi + g * 16);
        cp16(tb + BLO_O + sw[g], (const char*)pBlo + g * 16);
    }
    CP_COMMIT();

    for (int chunk = 0; chunk < 16; chunk++) {
        const uint32_t bufb = tb + (chunk & 1) * 65536;
        if (chunk < 15) {
            // Issue next chunk into the other buffer (its readers drained at
            // the bottom __syncthreads of the previous iteration).
            const uint32_t nb = tb + ((chunk + 1) & 1) * 65536;
            const size_t ko = (size_t)(chunk + 1) * 64;
#pragma unroll
            for (int g = 0; g < 4; g++) {
                cp16(nb + AHI_O + sw[g], (const char*)(pAhi + ko) + g * 16);
                cp16(nb + ALO_O + sw[g], (const char*)(pAlo + ko) + g * 16);
                cp16(nb + BHI_O + sw[g], (const char*)(pBhi + ko) + g * 16);
                cp16(nb + BLO_O + sw[g], (const char*)(pBlo + ko) + g * 16);
            }
            CP_COMMIT();
            cp_wait<1>();   // this chunk's group complete; next stays in flight
        } else {
            cp_wait<0>();
        }
        __syncthreads();

#pragma unroll
        for (int ks = 0; ks < 4; ks++) {
            uint32_t Ah[2][4], Al[2][4];
#pragma unroll
            for (int mi = 0; mi < 2; mi++) {
                const int r = wm + mi * 16 + (lane & 15);
                uint32_t off = (uint32_t)(r * 128 + ks * 32 + (lane >> 4) * 16);
                off ^= (off >> 3) & 0x70;
                ldsm4(Ah[mi], bufb + AHI_O + off);
                ldsm4(Al[mi], bufb + ALO_O + off);
            }
#pragma unroll
            for (int ni = 0; ni < 8; ni++) {
                const int n = wn + ni * 8 + (lane & 7);
                uint32_t off = (uint32_t)(n * 128 + ks * 32 + ((lane >> 3) & 1) * 16);
                off ^= (off >> 3) & 0x70;
                uint32_t Bh[2], Bl[2];
                ldsm2(Bh, bufb + BHI_O + off);
                ldsm2(Bl, bufb + BLO_O + off);
#pragma unroll
                for (int mi = 0; mi < 2; mi++) {
                    mma_bf16(acc[mi][ni], Ah[mi], Bh);
                    mma_bf16(acc[mi][ni], Ah[mi], Bl);
                    mma_bf16(acc[mi][ni], Al[mi], Bh);
                }
            }
        }
        __syncthreads();
    }

    // Epilogue: d0,d1 = (r, c..c+1), d2,d3 = (r+8, c..c+1)
#pragma unroll
    for (int mi = 0; mi < 2; mi++)
#pragma unroll
    for (int ni = 0; ni < 8; ni++) {
        const int rloc = wm + mi * 16 + (lane >> 2);
        const int c = wn + ni * 8 + (lane & 3) * 2;
        const int colb = n0 + c;
        const float2 b2 = *(const float2*)(bias + colb);
#pragma unroll
        for (int rr = 0; rr < 2; rr++) {
            const int rowm = m0 + rloc + rr * 8;
            float2 v;
            v.x = acc[mi][ni][rr * 2 + 0] + b2.x;
            v.y = acc[mi][ni][rr * 2 + 1] + b2.y;
            if (MODE == 1) {
                const int which = colb >> 10;       // 0=q, 1=k, 2=v (tile-constant)
                const int e  = colb & 1023;
                const int h  = e >> 6, db = e & 63; // db even -> 8B aligned
                const int b  = rowm >> 11, s = rowm & 2047;
                const size_t idx = ((size_t)((b * 16 + h) * 2048 + s)) * 64 + db;
                if (which == 0) {
                    v.x *= 0.125f; v.y *= 0.125f;   // fold 1/sqrt(64)
                    *(float2*)&g_q[idx] = v;
                } else if (which == 1) {
                    *(float2*)&g_k[idx] = v;
                } else {
                    *(float2*)&g_v[idx] = v;
                }
            } else {
                *(float2*)&Cout[(size_t)rowm * 1024 + colb] = v;
            }
        }
    }
}

// ---------------------------------------------------------------------------
// Flash attention, causal (unchanged from the PASSING R10 kernel).
// ---------------------------------------------------------------------------
#define ATTN_SMEM_BYTES (112 * 1024)

__global__ void __launch_bounds__(256, 2)
attn_kernel()
{
    extern __shared__ float smem[];
    float* Qd = smem;                  // [d][2r swizzled-by-pair]  8192 floats
    float* Ks = smem + 8192;           // [d][c^swz(d)]             4096 floats
    float* Vs = smem + 12288;          // [2][c][d']                8192 floats
    float* Pd = smem + 20480;          // [r][2c duplicated]        8192 floats

    const int tid = threadIdx.x;
    const int tm = tid >> 4, tn = tid & 15;
    const int qt = gridDim.x - 1 - blockIdx.x;  // heavy tiles launch first
    const int bh = blockIdx.y;
    const int q0 = qt * 64;
    const float* Qg = g_q + ((size_t)bh*2048 + q0) * 64;
    const float* Kg = g_k + (size_t)bh * 2048 * 64;
    const float* Vg = g_v + (size_t)bh * 2048 * 64;

    const int plr  = tid >> 4;
    const int pd4  = (tid & 15) << 2;
    const int pswz = ((pd4 >> 2) & 7) << 2;

#pragma unroll
    for (int it = 0; it < 4; it++) {
        const int rr = plr + it*16;
        float4 v = *(const float4*)(Qg + (size_t)rr*64 + pd4);
        const int col2 = (rr ^ pswz) << 1;
        *(float2*)&Qd[(pd4+0)*128 + col2] = make_float2(v.x, v.x);
        *(float2*)&Qd[(pd4+1)*128 + col2] = make_float2(v.y, v.y);
        *(float2*)&Qd[(pd4+2)*128 + col2] = make_float2(v.z, v.z);
        *(float2*)&Qd[(pd4+3)*128 + col2] = make_float2(v.w, v.w);
    }

    float mrow[4], lrow[4];
    unsigned long long O2[4][2];
#pragma unroll
    for (int i = 0; i < 4; i++) {
        mrow[i] = -1e30f; lrow[i] = 0.f;
        O2[i][0] = f32x2_pack(0.f, 0.f);
        O2[i][1] = f32x2_pack(0.f, 0.f);
    }

    float4 pk[4], pv[4];
#pragma unroll
    for (int it = 0; it < 4; it++) {
        pk[it] = *(const float4*)(Kg + (size_t)(plr + it*16)*64 + pd4);
        const int idx = tid + it*256;
        pv[it] = *(const float4*)(Vg + (size_t)(idx >> 4)*64 + ((idx & 15) << 2));
    }

    for (int jt = 0; jt <= qt; jt++) {
        float* Vcur = Vs + (jt & 1) * 4096;
#pragma unroll
        for (int it = 0; it < 4; it++) {
            const int rr = plr + it*16;
            const int col = rr ^ pswz;
            Ks[(pd4+0)*64 + col] = pk[it].x;
            Ks[(pd4+1)*64 + col] = pk[it].y;
            Ks[(pd4+2)*64 + col] = pk[it].z;
            Ks[(pd4+3)*64 + col] = pk[it].w;
            const int idx = tid + it*256;
            *(float4*)&Vcur[(idx >> 4)*64 + ((idx & 15) << 2)] = pv[it];
        }
        __syncthreads();  // commit-sync

        if (jt < qt) {
            const int k1 = (jt + 1) * 64;
#pragma unroll
            for (int it = 0; it < 4; it++) {
                pk[it] = *(const float4*)(Kg + (size_t)(k1 + plr + it*16)*64 + pd4);
                const int idx = tid + it*256;
                pv[it] = *(const float4*)(Vg + (size_t)(k1 + (idx >> 4))*64 + ((idx & 15) << 2));
            }
        }

        unsigned long long sacc2[4][2];
#pragma unroll
        for (int i = 0; i < 4; i++) {
            sacc2[i][0] = f32x2_pack(0.f, 0.f);
            sacc2[i][1] = f32x2_pack(0.f, 0.f);
        }

#pragma unroll
        for (int d4 = 0; d4 < 16; d4++) {
            const int swz = (d4 & 7) << 2;
            const int qb = ((tm*4) ^ swz) << 1;
            const int kcol = (tn*4) ^ swz;
#pragma unroll
            for (int dd = 0; dd < 4; dd++) {
                const int d = d4*4 + dd;
                const ulonglong2 q01 = *(const ulonglong2*)&Qd[d*128 + qb];
                const ulonglong2 q23 = *(const ulonglong2*)&Qd[d*128 + qb + 4];
                const ulonglong2 kk  = *(const ulonglong2*)&Ks[d*64 + kcol];
                f32x2_fma(sacc2[0][0], q01.x, kk.x);
                f32x2_fma(sacc2[0][1], q01.x, kk.y);
                f32x2_fma(sacc2[1][0], q01.y, kk.x);
                f32x2_fma(sacc2[1][1], q01.y, kk.y);
                f32x2_fma(sacc2[2][0], q23.x, kk.x);
                f32x2_fma(sacc2[2][1], q23.x, kk.y);
                f32x2_fma(sacc2[3][0], q23.y, kk.x);
                f32x2_fma(sacc2[3][1], q23.y, kk.y);
            }
        }

        float sacc[4][4];
#pragma unroll
        for (int i = 0; i < 4; i++) {
            f32x2_unpack(sacc[i][0], sacc[i][1], sacc2[i][0]);
            f32x2_unpack(sacc[i][2], sacc[i][3], sacc2[i][1]);
        }

        if (jt == qt) {
#pragma unroll
            for (int i = 0; i < 4; i++)
#pragma unroll
                for (int j2 = 0; j2 < 4; j2++)
                    if (tn*4 + j2 > tm*4 + i) sacc[i][j2] = -1e30f;
        }

#pragma unroll
        for (int i = 0; i < 4; i++) {
            float mx = fmaxf(fmaxf(sacc[i][0], sacc[i][1]), fmaxf(sacc[i][2], sacc[i][3]));
#pragma unroll
            for (int off = 8; off >= 1; off >>= 1)
                mx = fmaxf(mx, __shfl_xor_sync(0xffffffffu, mx, off, 16));
            const float mnew  = fmaxf(mrow[i], mx);
            const float alpha = __expf(mrow[i] - mnew);
            float rs = 0.f;
#pragma unroll
            for (int j2 = 0; j2 < 4; j2++) {
                const float p = __expf(sacc[i][j2] - mnew);
                sacc[i][j2] = p;
                rs += p;
            }
#pragma unroll
            for (int off = 8; off >= 1; off >>= 1)
                rs += __shfl_xor_sync(0xffffffffu, rs, off, 16);
            lrow[i] = lrow[i]*alpha + rs;
            mrow[i] = mnew;
            const unsigned long long ap = f32x2_pack(alpha, alpha);
            f32x2_mul(O2[i][0], O2[i][0], ap);
            f32x2_mul(O2[i][1], O2[i][1], ap);
        }

#pragma unroll
        for (int i = 0; i < 4; i++) {
            const int rb = (tm*4 + i)*128 + tn*8;
            *(float4*)&Pd[rb]     = make_float4(sacc[i][0], sacc[i][0], sacc[i][1], sacc[i][1]);
            *(float4*)&Pd[rb + 4] = make_float4(sacc[i][2], sacc[i][2], sacc[i][3], sacc[i][3]);
        }
        __syncthreads();  // p-sync

#pragma unroll 4
        for (int cb = 0; cb < 64; cb += 4) {
            ulonglong2 pA[4], pB[4];
#pragma unroll
            for (int i = 0; i < 4; i++) {
                const int rb = (tm*4 + i)*128 + cb*2;
                pA[i] = *(const ulonglong2*)&Pd[rb];
                pB[i] = *(const ulonglong2*)&Pd[rb + 4];
            }
#pragma unroll
            for (int cc = 0; cc < 4; cc++) {
                const ulonglong2 vv = *(const ulonglong2*)&Vcur[(cb+cc)*64 + tn*4];
#pragma unroll
                for (int i = 0; i < 4; i++) {
                    const unsigned long long pp =
                        cc == 0 ? pA[i].x : cc == 1 ? pA[i].y : cc == 2 ? pB[i].x : pB[i].y;
                    f32x2_fma(O2[i][0], pp, vv.x);
                    f32x2_fma(O2[i][1], pp, vv.y);
                }
            }
        }
    }

    const int b = bh >> 4, h = bh & 15;
#pragma unroll
    for (int i = 0; i < 4; i++) {
        const float inv = 1.f / lrow[i];
        const int s = q0 + tm*4 + i;
        float o0, o1, o2, o3;
        f32x2_unpack(o0, o1, O2[i][0]);
        f32x2_unpack(o2, o3, O2[i][1]);
        float4 v = make_float4(o0*inv, o1*inv, o2*inv, o3*inv);
        *(float4*)&g_attn[((size_t)(b*2048 + s))*1024 + h*64 + tn*4] = v;
    }
}

// ---------------------------------------------------------------------------
extern "C" void kernel_launch(void* const* d_in, const int* in_sizes, int n_in,
                              void* d_out, int out_size)
{
    (void)in_sizes; (void)n_in; (void)out_size;
    const float* query = (const float*)d_in[0];  // [4,2048,1024]
    const float* w_in  = (const float*)d_in[1];  // [3072,1024]
    const float* b_in  = (const float*)d_in[2];  // [3072]
    const float* w_out = (const float*)d_in[3];  // [1024,1024]
    const float* b_out = (const float*)d_in[4];  // [1024]
    float* out = (float*)d_out;                  // [4,2048,1024] fp32

    cudaFuncSetAttribute(attn_kernel,
                         cudaFuncAttributeMaxDynamicSharedMemorySize, ATTN_SMEM_BYTES);
    cudaFuncSetAttribute(mma_gemm<1>,
                         cudaFuncAttributeMaxDynamicSharedMemorySize, MG_SMEM_BYTES);
    cudaFuncSetAttribute(mma_gemm<2>,
                         cudaFuncAttributeMaxDynamicSharedMemorySize, MG_SMEM_BYTES);

    // 0) fp32 -> bf16 hi/lo splits
    convert_kernel<0><<<8192, 256>>>(query, 2097152);
    convert_kernel<1><<<3072, 256>>>(w_in,  786432);
    convert_kernel<2><<<1024, 256>>>(w_out, 262144);
    // 1) QKV projection (warp-mma bf16x3) + bias + q-scale + scatter
    mma_gemm<1><<<dim3(24, 64), 256, MG_SMEM_BYTES>>>(b_in, nullptr);
    // 2) causal flash attention -> g_attn
    attn_kernel<<<dim3(32, 64), 256, ATTN_SMEM_BYTES>>>();
    // 3) split attention output, then output projection (warp-mma bf16x3)
    convert_kernel<3><<<8192, 256>>>(nullptr, 2097152);
    mma_gemm<2><<<dim3(8, 64), 256, MG_SMEM_BYTES>>>(b_out, out);
}